// round 4
// baseline (speedup 1.0000x reference)
#include <cuda_runtime.h>
#include <cuda_bf16.h>
#include <cstdint>

// Problem constants: N_NODES=50000, N_EDGES=640000, D=128, OUT=1
#define MAX_NODES 50000
#define D 128

// Scratch (no cudaMalloc allowed)
__device__ float d_s1[MAX_NODES];
__device__ float d_s2[MAX_NODES];

__device__ __forceinline__ float dot4(float4 a, float4 b) {
    return a.x * b.x + a.y * b.y + a.z * b.z + a.w * b.w;
}

// Kernel 1: s1[n] = dot(X[n], W1), s2[n] = dot(X[n], W2).
// 4 nodes per warp, 8 lanes per node; each lane loads 4 consecutive float4s
// (16 floats) of its node's row -> 4 front-batched LDG.128 (MLP_p1 = 4).
__global__ void node_proj_kernel(const float* __restrict__ X,
                                 const float* __restrict__ W1,
                                 const float* __restrict__ W2,
                                 int n_nodes) {
    __shared__ __align__(16) float sW1[D];
    __shared__ __align__(16) float sW2[D];
    int tid = threadIdx.x;
    if (tid < D) {
        sW1[tid] = W1[tid];
        sW2[tid] = W2[tid];
    }
    __syncthreads();

    int lane = tid & 31;
    int sub  = lane & 7;          // position within the 8-lane group
    int grp  = lane >> 3;         // which of 4 nodes in this warp
    int gwarp = (blockIdx.x * blockDim.x + tid) >> 5;
    int node = gwarp * 4 + grp;
    if (node >= n_nodes) return;

    // Each lane covers floats [sub*16, sub*16+16) of the row.
    const float4* row = reinterpret_cast<const float4*>(X + (size_t)node * D) + sub * 4;
    float4 x0 = row[0];
    float4 x1 = row[1];
    float4 x2 = row[2];
    float4 x3 = row[3];

    const float4* w1 = reinterpret_cast<const float4*>(sW1) + sub * 4;
    const float4* w2 = reinterpret_cast<const float4*>(sW2) + sub * 4;

    float a = dot4(x0, w1[0]) + dot4(x1, w1[1]) + dot4(x2, w1[2]) + dot4(x3, w1[3]);
    float b = dot4(x0, w2[0]) + dot4(x1, w2[1]) + dot4(x2, w2[2]) + dot4(x3, w2[3]);

    // Reduce across the 8-lane group (xor offsets stay within the group).
    #pragma unroll
    for (int off = 4; off > 0; off >>= 1) {
        a += __shfl_xor_sync(0xFFFFFFFF, a, off);
        b += __shfl_xor_sync(0xFFFFFFFF, b, off);
    }

    if (sub == 0) {
        d_s1[node] = a;
        d_s2[node] = b;
    }
}

// Kernel 2: out[e] = s1[src[e]] + s2[dst[e]], int32 indices, 2 edges/thread.
// 2 edges/thread -> 10K warps (~64 warps/SM) for latency hiding on gathers.
__global__ void edge_kernel2(const int* __restrict__ ei,
                             float* __restrict__ out,
                             int n_edges) {
    int p = blockIdx.x * blockDim.x + threadIdx.x;
    int e0 = p * 2;
    if (e0 + 1 < n_edges) {
        int2 sv = *reinterpret_cast<const int2*>(ei + e0);
        int2 dv = *reinterpret_cast<const int2*>(ei + n_edges + e0);
        int sx = min(max(sv.x, 0), MAX_NODES - 1);
        int sy = min(max(sv.y, 0), MAX_NODES - 1);
        int dx = min(max(dv.x, 0), MAX_NODES - 1);
        int dy = min(max(dv.y, 0), MAX_NODES - 1);
        float2 r;
        r.x = d_s1[sx] + d_s2[dx];
        r.y = d_s1[sy] + d_s2[dy];
        *reinterpret_cast<float2*>(out + e0) = r;
    } else if (e0 < n_edges) {
        int s = min(max(ei[e0], 0), MAX_NODES - 1);
        int d = min(max(ei[n_edges + e0], 0), MAX_NODES - 1);
        out[e0] = d_s1[s] + d_s2[d];
    }
}

extern "C" void kernel_launch(void* const* d_in, const int* in_sizes, int n_in,
                              void* d_out, int out_size) {
    const float* X  = (const float*)d_in[0];
    const int*   ei = (const int*)d_in[1];     // [2, E] int32 (verified in R1/R2)
    const float* W1 = (const float*)d_in[2];
    const float* W2 = (const float*)d_in[3];
    float* out = (float*)d_out;

    int n_nodes = in_sizes[0] / D;             // 50000
    int n_edges = in_sizes[1] / 2;             // 640000

    // Kernel 1: 4 nodes per warp, 256 threads/block = 32 nodes/block
    int threads1 = 256;
    int nodes_per_block = (threads1 / 32) * 4;
    int blocks1 = (n_nodes + nodes_per_block - 1) / nodes_per_block;
    node_proj_kernel<<<blocks1, threads1>>>(X, W1, W2, n_nodes);

    // Kernel 2: 2 edges per thread
    int threads2 = 256;
    int pairs = (n_edges + 1) / 2;
    int blocks2 = (pairs + threads2 - 1) / threads2;
    edge_kernel2<<<blocks2, threads2>>>(ei, out, n_edges);
}

// round 5
// speedup vs baseline: 1.2243x; 1.2243x over previous
#include <cuda_runtime.h>
#include <cuda_bf16.h>
#include <cstdint>

// Problem constants: N_NODES=50000, N_EDGES=640000, D=128, OUT=1
#define MAX_NODES 50000
#define D 128

__device__ float d_s1[MAX_NODES];
__device__ float d_s2[MAX_NODES];

__device__ __forceinline__ float dot4(float4 a, float4 b) {
    return a.x * b.x + a.y * b.y + a.z * b.z + a.w * b.w;
}

// Kernel 1: s1[n] = dot(X[n], W1), s2[n] = dot(X[n], W2).
// 4 nodes per warp. Each of the 4 row loads is a FULL-warp coalesced LDG.128
// (lane l reads row_i[l*4..l*4+4)), all 4 front-batched => MLP_p1=4 with
// perfect coalescing (4 full 128B lines per LDG).
__global__ void node_proj_kernel(const float* __restrict__ X,
                                 const float* __restrict__ W1,
                                 const float* __restrict__ W2,
                                 int n_nodes) {
    __shared__ __align__(16) float sW1[D];
    __shared__ __align__(16) float sW2[D];
    int tid = threadIdx.x;
    if (tid < D) {
        sW1[tid] = W1[tid];
        sW2[tid] = W2[tid];
    }
    __syncthreads();

    int lane = tid & 31;
    int gwarp = (blockIdx.x * blockDim.x + tid) >> 5;
    int n0 = gwarp * 4;
    if (n0 >= n_nodes) return;

    const float4* base = reinterpret_cast<const float4*>(X) + (size_t)n0 * (D / 4) + lane;
    // 4 independent, fully-coalesced row loads (front-batched by ptxas).
    float4 x0 = base[0 * (D / 4)];
    float4 x1 = base[1 * (D / 4)];
    float4 x2 = base[2 * (D / 4)];
    float4 x3 = base[3 * (D / 4)];

    float4 w1v = reinterpret_cast<const float4*>(sW1)[lane];
    float4 w2v = reinterpret_cast<const float4*>(sW2)[lane];

    float a0 = dot4(x0, w1v), b0 = dot4(x0, w2v);
    float a1 = dot4(x1, w1v), b1 = dot4(x1, w2v);
    float a2 = dot4(x2, w1v), b2 = dot4(x2, w2v);
    float a3 = dot4(x3, w1v), b3 = dot4(x3, w2v);

    #pragma unroll
    for (int off = 16; off > 0; off >>= 1) {
        a0 += __shfl_xor_sync(0xFFFFFFFF, a0, off);
        b0 += __shfl_xor_sync(0xFFFFFFFF, b0, off);
        a1 += __shfl_xor_sync(0xFFFFFFFF, a1, off);
        b1 += __shfl_xor_sync(0xFFFFFFFF, b1, off);
        a2 += __shfl_xor_sync(0xFFFFFFFF, a2, off);
        b2 += __shfl_xor_sync(0xFFFFFFFF, b2, off);
        a3 += __shfl_xor_sync(0xFFFFFFFF, a3, off);
        b3 += __shfl_xor_sync(0xFFFFFFFF, b3, off);
    }

    if (lane == 0) {
        d_s1[n0]     = a0;  d_s2[n0]     = b0;
        if (n0 + 1 < n_nodes) { d_s1[n0 + 1] = a1;  d_s2[n0 + 1] = b1; }
        if (n0 + 2 < n_nodes) { d_s1[n0 + 2] = a2;  d_s2[n0 + 2] = b2; }
        if (n0 + 3 < n_nodes) { d_s1[n0 + 3] = a3;  d_s2[n0 + 3] = b3; }
    }
}

#define CLAMP(v) min(max((v), 0), MAX_NODES - 1)

// Kernel 2: out[e] = s1[src[e]] + s2[dst[e]], int32 indices, 8 edges/thread.
// All 4 index loads (int4) front-batched, then 16 independent gathers.
__global__ void edge_kernel8(const int* __restrict__ ei,
                             float* __restrict__ out,
                             int n_edges) {
    int p = blockIdx.x * blockDim.x + threadIdx.x;
    int e0 = p * 8;
    if (e0 + 7 < n_edges) {
        int4 sa = *reinterpret_cast<const int4*>(ei + e0);
        int4 sb = *reinterpret_cast<const int4*>(ei + e0 + 4);
        int4 da = *reinterpret_cast<const int4*>(ei + n_edges + e0);
        int4 db = *reinterpret_cast<const int4*>(ei + n_edges + e0 + 4);

        float4 r0, r1;
        r0.x = d_s1[CLAMP(sa.x)] + d_s2[CLAMP(da.x)];
        r0.y = d_s1[CLAMP(sa.y)] + d_s2[CLAMP(da.y)];
        r0.z = d_s1[CLAMP(sa.z)] + d_s2[CLAMP(da.z)];
        r0.w = d_s1[CLAMP(sa.w)] + d_s2[CLAMP(da.w)];
        r1.x = d_s1[CLAMP(sb.x)] + d_s2[CLAMP(db.x)];
        r1.y = d_s1[CLAMP(sb.y)] + d_s2[CLAMP(db.y)];
        r1.z = d_s1[CLAMP(sb.z)] + d_s2[CLAMP(db.z)];
        r1.w = d_s1[CLAMP(sb.w)] + d_s2[CLAMP(db.w)];

        *reinterpret_cast<float4*>(out + e0)     = r0;
        *reinterpret_cast<float4*>(out + e0 + 4) = r1;
    } else {
        for (int e = e0; e < n_edges; e++) {
            int s = CLAMP(ei[e]);
            int d = CLAMP(ei[n_edges + e]);
            out[e] = d_s1[s] + d_s2[d];
        }
    }
}

extern "C" void kernel_launch(void* const* d_in, const int* in_sizes, int n_in,
                              void* d_out, int out_size) {
    const float* X  = (const float*)d_in[0];
    const int*   ei = (const int*)d_in[1];     // [2, E] int32
    const float* W1 = (const float*)d_in[2];
    const float* W2 = (const float*)d_in[3];
    float* out = (float*)d_out;

    int n_nodes = in_sizes[0] / D;             // 50000
    int n_edges = in_sizes[1] / 2;             // 640000

    // Kernel 1: 4 nodes/warp, 256 threads/block = 32 nodes/block
    int threads1 = 256;
    int nodes_per_block = 32;
    int blocks1 = (n_nodes + nodes_per_block - 1) / nodes_per_block;
    node_proj_kernel<<<blocks1, threads1>>>(X, W1, W2, n_nodes);

    // Kernel 2: 8 edges/thread
    int threads2 = 256;
    int octs = (n_edges + 7) / 8;
    int blocks2 = (octs + threads2 - 1) / threads2;
    edge_kernel8<<<blocks2, threads2>>>(ei, out, n_edges);
}